// round 1
// baseline (speedup 1.0000x reference)
#include <cuda_runtime.h>
#include <math.h>

#define TT 2048
#define DD 1024
#define HH 2048
#define EE 8

#define BM 64
#define BN 64
#define BK 16

// -------- device scratch (no runtime allocation allowed) --------
__device__ int   g_count[EE];
__device__ int   g_offset[EE];
__device__ int   g_tok[EE * TT];
__device__ float g_gw[EE * TT];
// 2*TT routed rows total (+64 pad rows for tile overreads), H columns
__device__ float g_h[(size_t)(2 * TT + 64) * HH];

// ----------------------------------------------------------------
__global__ void reset_kernel(float* __restrict__ out) {
    size_t i = (size_t)blockIdx.x * blockDim.x + threadIdx.x;
    if (i < (size_t)TT * DD) out[i] = 0.0f;
    if (i < EE) g_count[i] = 0;
}

// One warp per token: logits, top-2, softmax, push into expert lists.
__global__ void gate_kernel(const float* __restrict__ x,
                            const float* __restrict__ Wg,
                            const float* __restrict__ bg,
                            float* __restrict__ out_idx, int write_idx) {
    int warp = (blockIdx.x * blockDim.x + threadIdx.x) >> 5;
    int lane = threadIdx.x & 31;
    if (warp >= TT) return;
    const float* xr = x + (size_t)warp * DD;

    float acc[EE];
#pragma unroll
    for (int e = 0; e < EE; e++) acc[e] = 0.0f;

    for (int d = lane; d < DD; d += 32) {
        float xv = xr[d];
        const float* wr = Wg + (size_t)d * EE;
#pragma unroll
        for (int e = 0; e < EE; e++) acc[e] += xv * wr[e];
    }
#pragma unroll
    for (int off = 16; off > 0; off >>= 1) {
#pragma unroll
        for (int e = 0; e < EE; e++)
            acc[e] += __shfl_xor_sync(0xFFFFFFFFu, acc[e], off);
    }

    if (lane == 0) {
        float v[EE];
#pragma unroll
        for (int e = 0; e < EE; e++) v[e] = acc[e] + bg[e];
        // top-2, jax tie-break: lowest index wins (strict > keeps earlier index)
        int e0 = 0;
#pragma unroll
        for (int e = 1; e < EE; e++) if (v[e] > v[e0]) e0 = e;
        int e1 = -1;
#pragma unroll
        for (int e = 0; e < EE; e++)
            if (e != e0 && (e1 < 0 || v[e] > v[e1])) e1 = e;

        float a1 = expf(v[e1] - v[e0]);   // softmax over the 2 picked logits
        float s  = 1.0f + a1;
        float w0 = 1.0f / s;
        float w1 = a1 / s;

        int p0 = atomicAdd(&g_count[e0], 1);
        g_tok[e0 * TT + p0] = warp;
        g_gw [e0 * TT + p0] = w0;
        int p1 = atomicAdd(&g_count[e1], 1);
        g_tok[e1 * TT + p1] = warp;
        g_gw [e1 * TT + p1] = w1;

        if (write_idx) {
            out_idx[warp * 2 + 0] = (float)e0;
            out_idx[warp * 2 + 1] = (float)e1;
        }
    }
}

__global__ void prefix_kernel() {
    if (threadIdx.x == 0) {
        int s = 0;
#pragma unroll
        for (int e = 0; e < EE; e++) { g_offset[e] = s; s += g_count[e]; }
    }
}

__device__ __forceinline__ float gelu_tanh(float v) {
    float x3 = v * v * v;
    float t  = tanhf(0.7978845608028654f * (v + 0.044715f * x3));
    return 0.5f * v * (1.0f + t);
}

// Grouped GEMM 1: gather X rows -> gelu(X @ W1[e] + b1[e]) -> g_h
__global__ __launch_bounds__(256) void ffn1_kernel(const float* __restrict__ x,
                                                   const float* __restrict__ W1,
                                                   const float* __restrict__ b1) {
    const int e   = blockIdx.x >> 5;
    const int mt  = blockIdx.x & 31;
    const int cnt = g_count[e];
    const int m0  = mt * BM;
    if (m0 >= cnt) return;
    const int n0 = blockIdx.y * BN;

    __shared__ float As[BK][BM + 1];
    __shared__ float Bs[BK][BN];
    __shared__ int   stok[BM];

    const int tid = threadIdx.x;
    if (tid < BM) {
        int r = m0 + tid;
        stok[tid] = (r < cnt) ? g_tok[e * TT + r] : 0;
    }
    __syncthreads();

    const float* Wb = W1 + (size_t)e * DD * HH;
    const int ty = tid >> 4, tx = tid & 15;
    const int am = tid >> 2;          // A row within tile
    const int ak = (tid & 3) * 4;     // A k-offset (float4)
    const int bk = tid >> 4;          // B k-row
    const int bn = (tid & 15) * 4;    // B n-offset (float4)

    float c[4][4];
#pragma unroll
    for (int i = 0; i < 4; i++)
#pragma unroll
        for (int j = 0; j < 4; j++) c[i][j] = 0.0f;

    const float* arow = x + (size_t)stok[am] * DD;

    for (int k = 0; k < DD; k += BK) {
        float4 av = *reinterpret_cast<const float4*>(arow + k + ak);
        As[ak + 0][am] = av.x; As[ak + 1][am] = av.y;
        As[ak + 2][am] = av.z; As[ak + 3][am] = av.w;
        float4 bv = *reinterpret_cast<const float4*>(&Wb[(size_t)(k + bk) * HH + n0 + bn]);
        *reinterpret_cast<float4*>(&Bs[bk][bn]) = bv;
        __syncthreads();
#pragma unroll
        for (int kk = 0; kk < BK; kk++) {
            float a[4], b[4];
#pragma unroll
            for (int i = 0; i < 4; i++) a[i] = As[kk][ty * 4 + i];
            float4 b4 = *reinterpret_cast<const float4*>(&Bs[kk][tx * 4]);
            b[0] = b4.x; b[1] = b4.y; b[2] = b4.z; b[3] = b4.w;
#pragma unroll
            for (int i = 0; i < 4; i++)
#pragma unroll
                for (int j = 0; j < 4; j++) c[i][j] += a[i] * b[j];
        }
        __syncthreads();
    }

    const int base = g_offset[e];
#pragma unroll
    for (int i = 0; i < 4; i++) {
        int r = m0 + ty * 4 + i;
        if (r < cnt) {
            float* hrow = &g_h[(size_t)(base + r) * HH + n0];
#pragma unroll
            for (int j = 0; j < 4; j++) {
                float v = c[i][j] + b1[e * HH + n0 + tx * 4 + j];
                hrow[tx * 4 + j] = gelu_tanh(v);
            }
        }
    }
}

// Grouped GEMM 2: g_h rows @ W2[e] + b2[e], scaled scatter-add into out
__global__ __launch_bounds__(256) void ffn2_kernel(const float* __restrict__ W2,
                                                   const float* __restrict__ b2,
                                                   float* __restrict__ out) {
    const int e   = blockIdx.x >> 5;
    const int mt  = blockIdx.x & 31;
    const int cnt = g_count[e];
    const int m0  = mt * BM;
    if (m0 >= cnt) return;
    const int n0 = blockIdx.y * BN;

    __shared__ float As[BK][BM + 1];
    __shared__ float Bs[BK][BN];
    __shared__ int   stok[BM];
    __shared__ float sw[BM];

    const int tid = threadIdx.x;
    if (tid < BM) {
        int r = m0 + tid;
        stok[tid] = (r < cnt) ? g_tok[e * TT + r] : 0;
        sw[tid]   = (r < cnt) ? g_gw [e * TT + r] : 0.0f;
    }
    __syncthreads();

    const int base = g_offset[e];
    const float* Wb = W2 + (size_t)e * HH * DD;
    const int ty = tid >> 4, tx = tid & 15;
    const int am = tid >> 2;
    const int ak = (tid & 3) * 4;
    const int bk = tid >> 4;
    const int bn = (tid & 15) * 4;

    float c[4][4];
#pragma unroll
    for (int i = 0; i < 4; i++)
#pragma unroll
        for (int j = 0; j < 4; j++) c[i][j] = 0.0f;

    const float* arow = &g_h[(size_t)(base + m0 + am) * HH];

    for (int k = 0; k < HH; k += BK) {
        float4 av = *reinterpret_cast<const float4*>(arow + k + ak);
        As[ak + 0][am] = av.x; As[ak + 1][am] = av.y;
        As[ak + 2][am] = av.z; As[ak + 3][am] = av.w;
        float4 bv = *reinterpret_cast<const float4*>(&Wb[(size_t)(k + bk) * DD + n0 + bn]);
        *reinterpret_cast<float4*>(&Bs[bk][bn]) = bv;
        __syncthreads();
#pragma unroll
        for (int kk = 0; kk < BK; kk++) {
            float a[4], b[4];
#pragma unroll
            for (int i = 0; i < 4; i++) a[i] = As[kk][ty * 4 + i];
            float4 b4 = *reinterpret_cast<const float4*>(&Bs[kk][tx * 4]);
            b[0] = b4.x; b[1] = b4.y; b[2] = b4.z; b[3] = b4.w;
#pragma unroll
            for (int i = 0; i < 4; i++)
#pragma unroll
                for (int j = 0; j < 4; j++) c[i][j] += a[i] * b[j];
        }
        __syncthreads();
    }

#pragma unroll
    for (int i = 0; i < 4; i++) {
        int r = m0 + ty * 4 + i;
        if (r < cnt) {
            int   t   = stok[ty * 4 + i];
            float wgt = sw[ty * 4 + i];
            float* orow = out + (size_t)t * DD + n0;
#pragma unroll
            for (int j = 0; j < 4; j++) {
                float v = c[i][j] + b2[e * DD + n0 + tx * 4 + j];
                atomicAdd(&orow[tx * 4 + j], wgt * v);
            }
        }
    }
}

// ----------------------------------------------------------------
extern "C" void kernel_launch(void* const* d_in, const int* in_sizes, int n_in,
                              void* d_out, int out_size) {
    const float* x  = (const float*)d_in[0];
    const float* Wg = (const float*)d_in[1];
    const float* bg = (const float*)d_in[2];
    const float* W1 = (const float*)d_in[3];
    const float* b1 = (const float*)d_in[4];
    const float* W2 = (const float*)d_in[5];
    const float* b2 = (const float*)d_in[6];
    float* out = (float*)d_out;

    const int write_idx = (out_size >= TT * DD + 2 * TT) ? 1 : 0;
    float* out_idx = out + (size_t)TT * DD;

    {   // zero output + counters
        int total = TT * DD;
        reset_kernel<<<(total + 255) / 256, 256>>>(out);
    }
    gate_kernel<<<(TT * 32 + 255) / 256, 256>>>(x, Wg, bg, out_idx, write_idx);
    prefix_kernel<<<1, 32>>>();

    dim3 g1(EE * (TT / BM), HH / BN);
    ffn1_kernel<<<g1, 256>>>(x, W1, b1);

    dim3 g2(EE * (TT / BM), DD / BN);
    ffn2_kernel<<<g2, 256>>>(W2, b2, out);
}

// round 3
// speedup vs baseline: 3.1288x; 3.1288x over previous
#include <cuda_runtime.h>
#include <math.h>
#include <stdint.h>

#define TT 2048
#define DD 1024
#define HH 2048
#define EE 8

#define BM 128
#define BN 128
#define BK 32
#define NTHREADS 256

// SMEM (uint32 words): A [2][128][36], B [2][32][136]
#define A_STRIDE 36
#define B_STRIDE 136
#define A_BUF_W (BM * A_STRIDE)          // 4608 words
#define B_BUF_W (BK * B_STRIDE)          // 4352 words
#define SMEM_WORDS (2 * A_BUF_W + 2 * B_BUF_W)
#define SMEM_DYN (SMEM_WORDS * 4)        // 71680 bytes

// -------- device scratch (no runtime allocation allowed) --------
__device__ int   g_count[EE];
__device__ int   g_offset[EE];
__device__ int   g_tok[EE * TT];
__device__ float g_gw[EE * TT];
__device__ __align__(256) float g_h[(size_t)(2 * TT + BM) * HH];

// ---------------- helpers ----------------
__device__ __forceinline__ uint32_t f2tf(float f) {
    uint32_t r;
    asm("cvt.rna.tf32.f32 %0, %1;" : "=r"(r) : "f"(f));
    return r;
}

__device__ __forceinline__ void mma_tf32(float* c, const uint32_t* a, const uint32_t* b) {
    asm volatile(
        "mma.sync.aligned.m16n8k8.row.col.f32.tf32.tf32.f32 "
        "{%0,%1,%2,%3}, {%4,%5,%6,%7}, {%8,%9}, {%0,%1,%2,%3};"
        : "+f"(c[0]), "+f"(c[1]), "+f"(c[2]), "+f"(c[3])
        : "r"(a[0]), "r"(a[1]), "r"(a[2]), "r"(a[3]), "r"(b[0]), "r"(b[1]));
}

__device__ __forceinline__ float gelu_tanh(float v) {
    float x3 = v * v * v;
    float t  = tanhf(0.7978845608028654f * (v + 0.044715f * x3));
    return 0.5f * v * (1.0f + t);
}

// ----------------------------------------------------------------
__global__ void reset_kernel(float* __restrict__ out) {
    size_t i = (size_t)blockIdx.x * blockDim.x + threadIdx.x;
    if (i < (size_t)TT * DD) out[i] = 0.0f;
    if (i < EE) g_count[i] = 0;
}

__global__ void gate_kernel(const float* __restrict__ x,
                            const float* __restrict__ Wg,
                            const float* __restrict__ bg,
                            float* __restrict__ out_idx, int write_idx) {
    int warp = (blockIdx.x * blockDim.x + threadIdx.x) >> 5;
    int lane = threadIdx.x & 31;
    if (warp >= TT) return;
    const float* xr = x + (size_t)warp * DD;

    float acc[EE];
#pragma unroll
    for (int e = 0; e < EE; e++) acc[e] = 0.0f;
    for (int d = lane; d < DD; d += 32) {
        float xv = xr[d];
        const float* wr = Wg + (size_t)d * EE;
#pragma unroll
        for (int e = 0; e < EE; e++) acc[e] += xv * wr[e];
    }
#pragma unroll
    for (int off = 16; off > 0; off >>= 1) {
#pragma unroll
        for (int e = 0; e < EE; e++)
            acc[e] += __shfl_xor_sync(0xFFFFFFFFu, acc[e], off);
    }
    if (lane == 0) {
        float v[EE];
#pragma unroll
        for (int e = 0; e < EE; e++) v[e] = acc[e] + bg[e];
        int e0 = 0;
#pragma unroll
        for (int e = 1; e < EE; e++) if (v[e] > v[e0]) e0 = e;
        int e1 = -1;
#pragma unroll
        for (int e = 0; e < EE; e++)
            if (e != e0 && (e1 < 0 || v[e] > v[e1])) e1 = e;

        float a1 = expf(v[e1] - v[e0]);
        float s  = 1.0f + a1;
        float w0 = 1.0f / s;
        float w1 = a1 / s;

        int p0 = atomicAdd(&g_count[e0], 1);
        g_tok[e0 * TT + p0] = warp;
        g_gw [e0 * TT + p0] = w0;
        int p1 = atomicAdd(&g_count[e1], 1);
        g_tok[e1 * TT + p1] = warp;
        g_gw [e1 * TT + p1] = w1;

        if (write_idx) {
            out_idx[warp * 2 + 0] = (float)e0;
            out_idx[warp * 2 + 1] = (float)e1;
        }
    }
}

__global__ void prefix_kernel() {
    if (threadIdx.x == 0) {
        int s = 0;
#pragma unroll
        for (int e = 0; e < EE; e++) { g_offset[e] = s; s += g_count[e]; }
    }
}

// ---------------- HMMA tf32 grouped FFN GEMM ----------------
// SECOND=false: ffn1  A = gathered x rows, B = W1[e] [DD,HH], epi: gelu(.+b1) -> g_h
// SECOND=true : ffn2  A = g_h rows,        B = W2[e] [HH,DD], epi: atomicAdd(w*(.+b2)) -> out
template <bool SECOND>
__global__ void __launch_bounds__(NTHREADS, 1)
ffn_kernel(const float* __restrict__ x,
           const float* __restrict__ W,
           const float* __restrict__ bias,
           float* __restrict__ out) {
    const int KDIM = SECOND ? HH : DD;
    const int NDIM = SECOND ? DD : HH;
    const int NS   = KDIM / BK;

    const int e   = blockIdx.x >> 4;
    const int mt_ = blockIdx.x & 15;
    const int cnt = g_count[e];
    const int m0  = mt_ * BM;
    if (m0 >= cnt) return;
    const int n0 = blockIdx.y * BN;
    const int gbase = g_offset[e];

    __shared__ int   stok[BM];
    __shared__ float swt[BM];
    extern __shared__ uint32_t smem[];
    uint32_t* const Asm = smem;                   // [2][BM][A_STRIDE]
    uint32_t* const Bsm = smem + 2 * A_BUF_W;     // [2][BK][B_STRIDE]

    const int tid  = threadIdx.x;
    const int lane = tid & 31;
    const int w    = tid >> 5;
    const int wm   = w & 3;        // 4 warps along M
    const int wn   = w >> 2;       // 2 warps along N

    if (tid < BM) {
        int r = m0 + tid;
        if (SECOND) {
            stok[tid] = (r < cnt) ? g_tok[e * TT + r] : 0;
            swt [tid] = (r < cnt) ? g_gw [e * TT + r] : 0.0f;
        } else {
            stok[tid] = (r < cnt) ? g_tok[e * TT + r] : g_tok[e * TT];
        }
    }
    __syncthreads();

    // ---- per-thread load assignments: 4 float4 of A, 4 float4 of B ----
    const float* ap[4];
    int aoff[4];
    const float* bp[4];
    int boff[4];
    const float* Wbase = W + (size_t)e * KDIM * NDIM;
#pragma unroll
    for (int i = 0; i < 4; i++) {
        int idx = tid + i * NTHREADS;        // 0..1023
        int ar  = idx >> 3;                  // row 0..127
        int ac  = (idx & 7) * 4;             // col 0..28
        if (SECOND)
            ap[i] = g_h + (size_t)(gbase + m0 + ar) * HH + ac;
        else
            ap[i] = x + (size_t)stok[ar] * DD + ac;
        aoff[i] = ar * A_STRIDE + ac;

        int bk = idx >> 5;                   // k 0..31
        int bc = (idx & 31) * 4;             // n 0..124
        bp[i]   = Wbase + (size_t)bk * NDIM + n0 + bc;
        boff[i] = bk * B_STRIDE + bc;
    }

    // ---- prologue: slab 0 ----
#pragma unroll
    for (int i = 0; i < 4; i++) {
        float4 va = *reinterpret_cast<const float4*>(ap[i]);
        uint4 ua = { f2tf(va.x), f2tf(va.y), f2tf(va.z), f2tf(va.w) };
        *reinterpret_cast<uint4*>(&Asm[aoff[i]]) = ua;
        float4 vb = *reinterpret_cast<const float4*>(bp[i]);
        uint4 ub = { f2tf(vb.x), f2tf(vb.y), f2tf(vb.z), f2tf(vb.w) };
        *reinterpret_cast<uint4*>(&Bsm[boff[i]]) = ub;
    }
    __syncthreads();

    float c[2][8][4];
#pragma unroll
    for (int m = 0; m < 2; m++)
#pragma unroll
        for (int n = 0; n < 8; n++)
#pragma unroll
            for (int j = 0; j < 4; j++) c[m][n][j] = 0.0f;

    const int lr = lane >> 2;   // 0..7
    const int lc = lane & 3;    // 0..3

    // ---- main loop ----
    for (int s = 0; s < NS; s++) {
        const int buf = s & 1;
        float4 pa[4], pb[4];
        if (s + 1 < NS) {
            const int koff = (s + 1) * BK;
#pragma unroll
            for (int i = 0; i < 4; i++) {
                pa[i] = *reinterpret_cast<const float4*>(ap[i] + koff);
                pb[i] = *reinterpret_cast<const float4*>(bp[i] + (size_t)koff * NDIM);
            }
        }

        const uint32_t* As = Asm + buf * A_BUF_W;
        const uint32_t* Bs = Bsm + buf * B_BUF_W;
#pragma unroll
        for (int ks = 0; ks < 4; ks++) {
            const int kk = ks * 8;
            uint32_t a[2][4], b[8][2];
#pragma unroll
            for (int m = 0; m < 2; m++) {
                int base = (wm * 32 + m * 16 + lr) * A_STRIDE + kk + lc;
                a[m][0] = As[base];
                a[m][1] = As[base + 8 * A_STRIDE];
                a[m][2] = As[base + 4];
                a[m][3] = As[base + 8 * A_STRIDE + 4];
            }
#pragma unroll
            for (int n = 0; n < 8; n++) {
                int base = (kk + lc) * B_STRIDE + wn * 64 + n * 8 + lr;
                b[n][0] = Bs[base];
                b[n][1] = Bs[base + 4 * B_STRIDE];
            }
#pragma unroll
            for (int m = 0; m < 2; m++)
#pragma unroll
                for (int n = 0; n < 8; n++)
                    mma_tf32(c[m][n], a[m], b[n]);
        }

        if (s + 1 < NS) {
            const int nb = buf ^ 1;
            uint32_t* Aw = Asm + nb * A_BUF_W;
            uint32_t* Bw = Bsm + nb * B_BUF_W;
#pragma unroll
            for (int i = 0; i < 4; i++) {
                uint4 ua = { f2tf(pa[i].x), f2tf(pa[i].y), f2tf(pa[i].z), f2tf(pa[i].w) };
                *reinterpret_cast<uint4*>(&Aw[aoff[i]]) = ua;
                uint4 ub = { f2tf(pb[i].x), f2tf(pb[i].y), f2tf(pb[i].z), f2tf(pb[i].w) };
                *reinterpret_cast<uint4*>(&Bw[boff[i]]) = ub;
            }
            __syncthreads();
        }
    }

    // ---- epilogue ----
    // D frag: c0 (row lr, col 2lc), c1 (row lr, col 2lc+1), c2/c3 (+8 rows)
#pragma unroll
    for (int n = 0; n < 8; n++) {
        const int coln = n0 + wn * 64 + n * 8 + 2 * lc;   // global col
        float bv0, bv1;
        if (SECOND) { bv0 = bias[e * DD + coln]; bv1 = bias[e * DD + coln + 1]; }
        else        { bv0 = bias[e * HH + coln]; bv1 = bias[e * HH + coln + 1]; }
#pragma unroll
        for (int m = 0; m < 2; m++) {
#pragma unroll
            for (int h = 0; h < 2; h++) {
                const int rloc = wm * 32 + m * 16 + h * 8 + lr;
                const int rg   = m0 + rloc;
                if (rg < cnt) {
                    float v0 = c[m][n][2 * h + 0] + bv0;
                    float v1 = c[m][n][2 * h + 1] + bv1;
                    if (!SECOND) {
                        float2 o = { gelu_tanh(v0), gelu_tanh(v1) };
                        *reinterpret_cast<float2*>(
                            &g_h[(size_t)(gbase + rg) * HH + coln]) = o;
                    } else {
                        const float wgt = swt[rloc];
                        float* op = out + (size_t)stok[rloc] * DD + coln;
                        atomicAdd(op + 0, wgt * v0);
                        atomicAdd(op + 1, wgt * v1);
                    }
                }
            }
        }
    }
}

// ----------------------------------------------------------------
extern "C" void kernel_launch(void* const* d_in, const int* in_sizes, int n_in,
                              void* d_out, int out_size) {
    const float* x  = (const float*)d_in[0];
    const float* Wg = (const float*)d_in[1];
    const float* bg = (const float*)d_in[2];
    const float* W1 = (const float*)d_in[3];
    const float* b1 = (const float*)d_in[4];
    const float* W2 = (const float*)d_in[5];
    const float* b2 = (const float*)d_in[6];
    float* out = (float*)d_out;

    const int write_idx = (out_size >= TT * DD + 2 * TT) ? 1 : 0;
    float* out_idx = out + (size_t)TT * DD;

    static int attr_done = 0;
    if (!attr_done) {
        cudaFuncSetAttribute(ffn_kernel<false>, cudaFuncAttributeMaxDynamicSharedMemorySize, SMEM_DYN);
        cudaFuncSetAttribute(ffn_kernel<true>,  cudaFuncAttributeMaxDynamicSharedMemorySize, SMEM_DYN);
        attr_done = 1;
    }

    reset_kernel<<<(TT * DD + 255) / 256, 256>>>(out);
    gate_kernel<<<(TT * 32 + 255) / 256, 256>>>(x, Wg, bg, out_idx, write_idx);
    prefix_kernel<<<1, 32>>>();

    ffn_kernel<false><<<dim3(EE * (TT / BM), HH / BN), NTHREADS, SMEM_DYN>>>(x, W1, b1, nullptr);
    ffn_kernel<true ><<<dim3(EE * (TT / BM), DD / BN), NTHREADS, SMEM_DYN>>>(x, W2, b2, out);
}

// round 4
// speedup vs baseline: 3.8894x; 1.2431x over previous
#include <cuda_runtime.h>
#include <math.h>
#include <stdint.h>

#define TT 2048
#define DD 1024
#define HH 2048
#define EE 8

#define BM 128
#define BN 128
#define BK 32
#define NTHREADS 128

// SMEM word layout: A [2][128][36], B [2][32][136]
#define A_STRIDE 36
#define B_STRIDE 136
#define A_BUF_W (BM * A_STRIDE)            // 4608
#define B_BUF_W (BK * B_STRIDE)            // 4352
#define SMEM_DYN ((2 * A_BUF_W + 2 * B_BUF_W) * 4)   // 71680 B

// -------- device scratch (no runtime allocation allowed) --------
__device__ int   g_count[EE];
__device__ int   g_offset[EE];
__device__ int   g_tok[EE * TT];
__device__ int   g_se[2 * TT];
__device__ int   g_sp[2 * TT];
__device__ float g_wt2[2 * TT];
__device__ __align__(16) float g_x[(size_t)TT * DD];                 // tf32-rounded x
__device__ __align__(16) float g_h[(size_t)(2 * TT + BM) * HH];      // gelu out (tf32-rounded)
__device__ __align__(16) float g_y[(size_t)(2 * TT) * DD];           // per-slot ffn2 out

// ---------------- helpers ----------------
__device__ __forceinline__ uint32_t smem_u32(const void* p) {
    uint32_t a;
    asm("{ .reg .u64 t; cvta.to.shared.u64 t, %1; cvt.u32.u64 %0, t; }" : "=r"(a) : "l"(p));
    return a;
}
__device__ __forceinline__ uint32_t f2tf(float f) {
    uint32_t r;
    asm("cvt.rna.tf32.f32 %0, %1;" : "=r"(r) : "f"(f));
    return r;
}
#define CP_ASYNC16(dst, src) \
    asm volatile("cp.async.cg.shared.global [%0], [%1], 16;" :: "r"(dst), "l"(src) : "memory")
#define CP_COMMIT()  asm volatile("cp.async.commit_group;" ::: "memory")
#define CP_WAIT0()   asm volatile("cp.async.wait_group 0;" ::: "memory")

__device__ __forceinline__ void mma_tf32(float* c, const uint32_t* a, const uint32_t* b) {
    asm volatile(
        "mma.sync.aligned.m16n8k8.row.col.f32.tf32.tf32.f32 "
        "{%0,%1,%2,%3}, {%4,%5,%6,%7}, {%8,%9}, {%0,%1,%2,%3};"
        : "+f"(c[0]), "+f"(c[1]), "+f"(c[2]), "+f"(c[3])
        : "r"(a[0]), "r"(a[1]), "r"(a[2]), "r"(a[3]), "r"(b[0]), "r"(b[1]));
}

__device__ __forceinline__ float gelu_tanh(float v) {
    float x3 = v * v * v;
    float t  = tanhf(0.7978845608028654f * (v + 0.044715f * x3));
    return 0.5f * v * (1.0f + t);
}

// ----------------------------------------------------------------
// prep: tf32-round x into g_x, zero counters
__global__ void prep_kernel(const float* __restrict__ x) {
    int i = blockIdx.x * blockDim.x + threadIdx.x;
    if (i < EE) g_count[i] = 0;
    const int n4 = TT * DD / 4;
    const int stride = gridDim.x * blockDim.x;
    for (int j = i; j < n4; j += stride) {
        float4 v = reinterpret_cast<const float4*>(x)[j];
        uint4 u = { f2tf(v.x), f2tf(v.y), f2tf(v.z), f2tf(v.w) };
        reinterpret_cast<uint4*>(g_x)[j] = u;
    }
}

__global__ void gate_kernel(const float* __restrict__ x,
                            const float* __restrict__ Wg,
                            const float* __restrict__ bg,
                            float* __restrict__ out_idx, int write_idx) {
    int warp = (blockIdx.x * blockDim.x + threadIdx.x) >> 5;
    int lane = threadIdx.x & 31;
    if (warp >= TT) return;
    const float* xr = x + (size_t)warp * DD;

    float acc[EE];
#pragma unroll
    for (int e = 0; e < EE; e++) acc[e] = 0.0f;
    for (int d = lane; d < DD; d += 32) {
        float xv = xr[d];
        const float* wr = Wg + (size_t)d * EE;
#pragma unroll
        for (int e = 0; e < EE; e++) acc[e] += xv * wr[e];
    }
#pragma unroll
    for (int off = 16; off > 0; off >>= 1) {
#pragma unroll
        for (int e = 0; e < EE; e++)
            acc[e] += __shfl_xor_sync(0xFFFFFFFFu, acc[e], off);
    }
    if (lane == 0) {
        float v[EE];
#pragma unroll
        for (int e = 0; e < EE; e++) v[e] = acc[e] + bg[e];
        int e0 = 0;
#pragma unroll
        for (int e = 1; e < EE; e++) if (v[e] > v[e0]) e0 = e;
        int e1 = -1;
#pragma unroll
        for (int e = 0; e < EE; e++)
            if (e != e0 && (e1 < 0 || v[e] > v[e1])) e1 = e;

        float a1 = expf(v[e1] - v[e0]);
        float s  = 1.0f + a1;
        float w0 = 1.0f / s;
        float w1 = a1 / s;

        int p0 = atomicAdd(&g_count[e0], 1);
        g_tok[e0 * TT + p0] = warp;
        int p1 = atomicAdd(&g_count[e1], 1);
        g_tok[e1 * TT + p1] = warp;

        g_se[2 * warp] = e0;  g_sp[2 * warp] = p0;  g_wt2[2 * warp] = w0;
        g_se[2 * warp + 1] = e1;  g_sp[2 * warp + 1] = p1;  g_wt2[2 * warp + 1] = w1;

        if (write_idx) {
            out_idx[warp * 2 + 0] = (float)e0;
            out_idx[warp * 2 + 1] = (float)e1;
        }
    }
}

__global__ void prefix_kernel() {
    if (threadIdx.x == 0) {
        int s = 0;
#pragma unroll
        for (int e = 0; e < EE; e++) { g_offset[e] = s; s += g_count[e]; }
    }
}

// ---------------- HMMA tf32 grouped FFN GEMM ----------------
// SECOND=false: A = g_x gathered rows, B = W1[e] [DD,HH], epi: tf32(gelu(.+b1)) -> g_h
// SECOND=true : A = g_h rows,          B = W2[e] [HH,DD], epi: (.+b2) -> g_y
template <bool SECOND>
__global__ void __launch_bounds__(NTHREADS, 2)
ffn_kernel(const float* __restrict__ W, const float* __restrict__ bias) {
    const int KDIM = SECOND ? HH : DD;
    const int NDIM = SECOND ? DD : HH;
    const int NS   = KDIM / BK;

    const int e   = blockIdx.x >> 4;
    const int mt_ = blockIdx.x & 15;
    const int cnt = g_count[e];
    const int m0  = mt_ * BM;
    if (m0 >= cnt) return;
    const int n0 = blockIdx.y * BN;
    const int gbase = g_offset[e];

    __shared__ int stok[BM];
    extern __shared__ uint32_t smem[];
    uint32_t* const Asm = smem;                   // [2][128][36]
    uint32_t* const Bsm = smem + 2 * A_BUF_W;     // [2][32][136]
    const uint32_t sbase = smem_u32(smem);

    const int tid  = threadIdx.x;
    const int lane = tid & 31;
    const int wid  = tid >> 5;
    const int wm   = wid & 1;      // 2 warps along M (64 rows each)
    const int wn   = wid >> 1;     // 2 warps along N (64 cols each)
    const int lr   = lane >> 2;    // 0..7
    const int lc   = lane & 3;     // 0..3

    if (!SECOND) {
        if (tid < BM) {
            int r = m0 + tid;
            stok[tid] = (r < cnt) ? g_tok[e * TT + r] : g_tok[e * TT];
        }
        __syncthreads();
    }

    // A producer: 8 chunks of 16B per thread per slab.
    // chunk i: row = (tid>>3)+16i, k-quad = (tid&7)*4
    const char* Agbase = SECOND ? (const char*)g_h : (const char*)g_x;
    uint32_t aoff[8];       // byte offset of row start in source
    uint32_t adst[8];       // byte SMEM address (buf 0)
#pragma unroll
    for (int i = 0; i < 8; i++) {
        const int row = (tid >> 3) + 16 * i;
        if (SECOND) aoff[i] = (uint32_t)((gbase + m0 + row) * HH * 4);
        else        aoff[i] = (uint32_t)(stok[row] * DD * 4);
        adst[i] = sbase + (uint32_t)((row * A_STRIDE + (tid & 7) * 4) * 4);
    }
    const uint32_t akq = (uint32_t)((tid & 7) * 16);   // byte offset within k-slab

    // B producer: 8 float4 per thread per slab. chunk i: k = (tid>>5)+4i, n-quad = (tid&31)*4
    const float* Wb = W + (size_t)e * KDIM * NDIM + n0 + (tid & 31) * 4;
    const int bk0 = tid >> 5;
    const int bw0 = bk0 * B_STRIDE + (tid & 31) * 4;   // word offset in B buf

    // ---- prologue: slab 0 ----
#pragma unroll
    for (int i = 0; i < 8; i++)
        CP_ASYNC16(adst[i], Agbase + aoff[i] + akq);
    CP_COMMIT();
    float4 pb[8];
#pragma unroll
    for (int i = 0; i < 8; i++)
        pb[i] = *reinterpret_cast<const float4*>(Wb + (size_t)(bk0 + 4 * i) * NDIM);
#pragma unroll
    for (int i = 0; i < 8; i++) {
        uint4 u = { f2tf(pb[i].x), f2tf(pb[i].y), f2tf(pb[i].z), f2tf(pb[i].w) };
        *reinterpret_cast<uint4*>(&Bsm[bw0 + i * 4 * B_STRIDE]) = u;
    }
    CP_WAIT0();
    __syncthreads();

    float c[4][8][4];
#pragma unroll
    for (int m = 0; m < 4; m++)
#pragma unroll
        for (int n = 0; n < 8; n++)
#pragma unroll
            for (int j = 0; j < 4; j++) c[m][n][j] = 0.0f;

    // ---- main loop ----
    for (int s = 0; s < NS; s++) {
        const int buf = s & 1;
        const int nb  = buf ^ 1;
        if (s + 1 < NS) {
            const uint32_t k0b = (uint32_t)((s + 1) * BK * 4);
#pragma unroll
            for (int i = 0; i < 8; i++)
                CP_ASYNC16(adst[i] + (uint32_t)(nb * A_BUF_W * 4), Agbase + aoff[i] + k0b + akq);
            CP_COMMIT();
            const int k0 = (s + 1) * BK;
#pragma unroll
            for (int i = 0; i < 8; i++)
                pb[i] = *reinterpret_cast<const float4*>(Wb + (size_t)(k0 + bk0 + 4 * i) * NDIM);
        }

        const uint32_t* As = Asm + buf * A_BUF_W;
        const uint32_t* Bs = Bsm + buf * B_BUF_W;
#pragma unroll
        for (int ks = 0; ks < 4; ks++) {
            const int kk = ks * 8;
            uint32_t a[4][4], b[8][2];
#pragma unroll
            for (int m = 0; m < 4; m++) {
                const int base = (wm * 64 + m * 16 + lr) * A_STRIDE + kk + lc;
                a[m][0] = As[base];
                a[m][1] = As[base + 8 * A_STRIDE];
                a[m][2] = As[base + 4];
                a[m][3] = As[base + 8 * A_STRIDE + 4];
            }
#pragma unroll
            for (int n = 0; n < 8; n++) {
                const int bb = (kk + lc) * B_STRIDE + wn * 64 + n * 8 + lr;
                b[n][0] = Bs[bb];
                b[n][1] = Bs[bb + 4 * B_STRIDE];
            }
#pragma unroll
            for (int m = 0; m < 4; m++)
#pragma unroll
                for (int n = 0; n < 8; n++)
                    mma_tf32(c[m][n], a[m], b[n]);
        }

        if (s + 1 < NS) {
            uint32_t* Bw = Bsm + nb * B_BUF_W;
#pragma unroll
            for (int i = 0; i < 8; i++) {
                uint4 u = { f2tf(pb[i].x), f2tf(pb[i].y), f2tf(pb[i].z), f2tf(pb[i].w) };
                *reinterpret_cast<uint4*>(&Bw[bw0 + i * 4 * B_STRIDE]) = u;
            }
            CP_WAIT0();
            __syncthreads();
        }
    }

    // ---- epilogue ----
#pragma unroll
    for (int n = 0; n < 8; n++) {
        const int col = n0 + wn * 64 + n * 8 + 2 * lc;
        const float bv0 = bias[e * NDIM + col];
        const float bv1 = bias[e * NDIM + col + 1];
#pragma unroll
        for (int m = 0; m < 4; m++) {
#pragma unroll
            for (int h = 0; h < 2; h++) {
                const int rloc = wm * 64 + m * 16 + h * 8 + lr;
                const int rg   = m0 + rloc;
                if (rg < cnt) {
                    float v0 = c[m][n][2 * h + 0] + bv0;
                    float v1 = c[m][n][2 * h + 1] + bv1;
                    if (!SECOND) {
                        // tf32-round gelu output so ffn2 can consume it raw
                        float2 o = { __uint_as_float(f2tf(gelu_tanh(v0))),
                                     __uint_as_float(f2tf(gelu_tanh(v1))) };
                        *reinterpret_cast<float2*>(&g_h[(size_t)(gbase + rg) * HH + col]) = o;
                    } else {
                        float2 o = { v0, v1 };
                        *reinterpret_cast<float2*>(&g_y[(size_t)(gbase + rg) * DD + col]) = o;
                    }
                }
            }
        }
    }
}

// combine: out[t] = w0*y[slot0] + w1*y[slot1]  (writes every element; no zero-init needed)
__global__ void combine_kernel(float* __restrict__ out) {
    const int t = blockIdx.x;
    __shared__ int   s0, s1;
    __shared__ float w0, w1;
    if (threadIdx.x == 0) {
        s0 = g_offset[g_se[2 * t]]     + g_sp[2 * t];
        s1 = g_offset[g_se[2 * t + 1]] + g_sp[2 * t + 1];
        w0 = g_wt2[2 * t];
        w1 = g_wt2[2 * t + 1];
    }
    __syncthreads();
    const int d = threadIdx.x;                  // DD/4 == 256 == blockDim
    float4 y0 = reinterpret_cast<const float4*>(g_y + (size_t)s0 * DD)[d];
    float4 y1 = reinterpret_cast<const float4*>(g_y + (size_t)s1 * DD)[d];
    float4 o = { w0 * y0.x + w1 * y1.x, w0 * y0.y + w1 * y1.y,
                 w0 * y0.z + w1 * y1.z, w0 * y0.w + w1 * y1.w };
    reinterpret_cast<float4*>(out + (size_t)t * DD)[d] = o;
}

// ----------------------------------------------------------------
extern "C" void kernel_launch(void* const* d_in, const int* in_sizes, int n_in,
                              void* d_out, int out_size) {
    const float* x  = (const float*)d_in[0];
    const float* Wg = (const float*)d_in[1];
    const float* bg = (const float*)d_in[2];
    const float* W1 = (const float*)d_in[3];
    const float* b1 = (const float*)d_in[4];
    const float* W2 = (const float*)d_in[5];
    const float* b2 = (const float*)d_in[6];
    float* out = (float*)d_out;

    const int write_idx = (out_size >= TT * DD + 2 * TT) ? 1 : 0;
    float* out_idx = out + (size_t)TT * DD;

    static int attr_done = 0;
    if (!attr_done) {
        cudaFuncSetAttribute(ffn_kernel<false>, cudaFuncAttributeMaxDynamicSharedMemorySize, SMEM_DYN);
        cudaFuncSetAttribute(ffn_kernel<true>,  cudaFuncAttributeMaxDynamicSharedMemorySize, SMEM_DYN);
        attr_done = 1;
    }

    prep_kernel<<<512, 256>>>(x);
    gate_kernel<<<(TT * 32 + 255) / 256, 256>>>(x, Wg, bg, out_idx, write_idx);
    prefix_kernel<<<1, 32>>>();

    ffn_kernel<false><<<dim3(EE * 16, HH / BN), NTHREADS, SMEM_DYN>>>(W1, b1);
    ffn_kernel<true ><<<dim3(EE * 16, DD / BN), NTHREADS, SMEM_DYN>>>(W2, b2);

    combine_kernel<<<TT, 256>>>(out);
}